// round 6
// baseline (speedup 1.0000x reference)
#include <cuda_runtime.h>
#include <cstdint>

// Problem constants
#define Bc 32
#define Tc 256
#define Hc 512
#define Vc 32000
#define NBLK 128   // persistent recurrence grid (<=148 SMs, 1 block/SM => co-resident)

// ---------------------------------------------------------------------------
// Scratch (device globals: allocation-free per harness rules)
// ---------------------------------------------------------------------------
__device__ float g_gi0[Tc * Bc * 3 * Hc];   // [t*B+b][3H] precomputed input gates L0 (50.3MB)
__device__ float g_outs[Bc * Tc * Hc];      // [b*T+t][H] GRU outputs (16.8MB)
__device__ float g_h[Bc * Hc];              // hidden (double-buffered with g_h1)
__device__ float g_h1[Bc * Hc];
__device__ unsigned g_barcnt;               // zero-init, self-resetting
__device__ unsigned g_bargen;

// ---------------------------------------------------------------------------
// Grid barrier (sense-reversing; safe across graph replays: counter ends at 0,
// generation is monotonic). All NBLK blocks are resident by construction.
// ---------------------------------------------------------------------------
__device__ __forceinline__ void gridbar() {
    __syncthreads();
    if (threadIdx.x == 0) {
        __threadfence();
        unsigned gen = *(volatile unsigned*)&g_bargen;
        if (atomicAdd(&g_barcnt, 1u) == NBLK - 1) {
            atomicExch(&g_barcnt, 0u);
            __threadfence();
            atomicAdd(&g_bargen, 1u);
        } else {
            while (*(volatile unsigned*)&g_bargen == gen) __nanosleep(64);
        }
        __threadfence();
    }
    __syncthreads();
}

__device__ __forceinline__ float sigm(float v) { return 1.f / (1.f + __expf(-v)); }

// ---------------------------------------------------------------------------
// Fused GEMM: C[m][n] = dot(Arow(m), W[n]) + bias[n]
//   A row-major [?,512], W row-major [N,512] (dot along K -> both K-contiguous)
//   MODE==1: Arow(m) = emb[x[b][t]] with m = t*32+b (embedding gather fused)
//   MODE==0: Arow(m) = A[m]
// Block tile 128x128, TK=16, 256 threads, 8x8 per thread.
// ---------------------------------------------------------------------------
template <int MODE>
__global__ void __launch_bounds__(256, 2)
gemm_tn(const float* __restrict__ A, const float* __restrict__ W,
        const float* __restrict__ bias, float* __restrict__ C,
        const int* __restrict__ xidx, int N)
{
    __shared__ float As[16 * 128];
    __shared__ float Bs[16 * 128];

    const int tid  = threadIdx.x;
    const int m0   = blockIdx.y * 128;
    const int n0   = blockIdx.x * 128;
    const int lrow = tid >> 2;          // 0..63
    const int lk   = (tid & 3) * 4;     // 0,4,8,12
    const int ty   = tid >> 4;          // 0..15 (m dim)
    const int tx   = tid & 15;          // 0..15 (n dim)

    const float *ap0, *ap1;
    {
        int ma0 = m0 + lrow, ma1 = ma0 + 64;
        if (MODE == 1) {
            int r0 = xidx[(ma0 & 31) * Tc + (ma0 >> 5)];
            int r1 = xidx[(ma1 & 31) * Tc + (ma1 >> 5)];
            ap0 = A + (size_t)r0 * Hc;
            ap1 = A + (size_t)r1 * Hc;
        } else {
            ap0 = A + (size_t)ma0 * Hc;
            ap1 = A + (size_t)ma1 * Hc;
        }
    }
    const float* bp0 = W + (size_t)(n0 + lrow) * Hc;
    const float* bp1 = bp0 + (size_t)64 * Hc;

    float acc[8][8];
#pragma unroll
    for (int i = 0; i < 8; i++)
#pragma unroll
        for (int j = 0; j < 8; j++) acc[i][j] = 0.f;

    for (int kt = 0; kt < Hc; kt += 16) {
        float4 a0 = *(const float4*)(ap0 + kt + lk);
        float4 a1 = *(const float4*)(ap1 + kt + lk);
        float4 b0 = *(const float4*)(bp0 + kt + lk);
        float4 b1 = *(const float4*)(bp1 + kt + lk);
        __syncthreads();
        As[(lk + 0) * 128 + lrow]      = a0.x;
        As[(lk + 1) * 128 + lrow]      = a0.y;
        As[(lk + 2) * 128 + lrow]      = a0.z;
        As[(lk + 3) * 128 + lrow]      = a0.w;
        As[(lk + 0) * 128 + lrow + 64] = a1.x;
        As[(lk + 1) * 128 + lrow + 64] = a1.y;
        As[(lk + 2) * 128 + lrow + 64] = a1.z;
        As[(lk + 3) * 128 + lrow + 64] = a1.w;
        Bs[(lk + 0) * 128 + lrow]      = b0.x;
        Bs[(lk + 1) * 128 + lrow]      = b0.y;
        Bs[(lk + 2) * 128 + lrow]      = b0.z;
        Bs[(lk + 3) * 128 + lrow]      = b0.w;
        Bs[(lk + 0) * 128 + lrow + 64] = b1.x;
        Bs[(lk + 1) * 128 + lrow + 64] = b1.y;
        Bs[(lk + 2) * 128 + lrow + 64] = b1.z;
        Bs[(lk + 3) * 128 + lrow + 64] = b1.w;
        __syncthreads();
#pragma unroll
        for (int kk = 0; kk < 16; kk++) {
            float4 av0 = *(const float4*)&As[kk * 128 + ty * 8];
            float4 av1 = *(const float4*)&As[kk * 128 + ty * 8 + 4];
            float4 bv0 = *(const float4*)&Bs[kk * 128 + tx * 8];
            float4 bv1 = *(const float4*)&Bs[kk * 128 + tx * 8 + 4];
            float a[8] = {av0.x, av0.y, av0.z, av0.w, av1.x, av1.y, av1.z, av1.w};
            float b[8] = {bv0.x, bv0.y, bv0.z, bv0.w, bv1.x, bv1.y, bv1.z, bv1.w};
#pragma unroll
            for (int i = 0; i < 8; i++)
#pragma unroll
                for (int j = 0; j < 8; j++) acc[i][j] += a[i] * b[j];
        }
    }

    float bs[8];
#pragma unroll
    for (int j = 0; j < 8; j++) bs[j] = bias[n0 + tx * 8 + j];
#pragma unroll
    for (int i = 0; i < 8; i++) {
        size_t base = (size_t)(m0 + ty * 8 + i) * (size_t)N + n0 + tx * 8;
        float4 o0 = make_float4(acc[i][0] + bs[0], acc[i][1] + bs[1],
                                acc[i][2] + bs[2], acc[i][3] + bs[3]);
        float4 o1 = make_float4(acc[i][4] + bs[4], acc[i][5] + bs[5],
                                acc[i][6] + bs[6], acc[i][7] + bs[7]);
        *(float4*)&C[base]     = o0;
        *(float4*)&C[base + 4] = o1;
    }
}

// ---------------------------------------------------------------------------
// Persistent GRU recurrence. 128 blocks x 256 threads.
// Block bk owns hidden units j in [4bk, 4bk+4). All weight rows this block
// ever needs (12 for phase 1, 24 for phase 2) live in SMEM for the entire
// kernel. h is broadcast via global (L2) with __ldcg (L1 not coherent across
// our barrier). Thread = (b in 0..31, jj in 0..3, khalf in 0..1); K split in
// two halves combined through SMEM.
// ---------------------------------------------------------------------------
#define REC_SMEM_FLOATS (12 * 512 + 24 * 512 + 512 * 33 + 768)

__global__ void __launch_bounds__(256, 1)
gru_rec(const float* __restrict__ Wih, const float* __restrict__ Whh,
        const float* __restrict__ bih, const float* __restrict__ bhh)
{
    extern __shared__ float sm[];
    float* ws1  = sm;                   // [12][512]  Whh0 rows (r,z,n per jj)
    float* ws2  = sm + 12 * 512;        // [24][512]  Wih1 r,z,n + Whh1 r,z,n per jj
    float* hs   = sm + 36 * 512;        // [512][33]  h transposed (padded)
    float* psum = hs + 512 * 33;        // [128][6]   k-half partials

    const int tid = threadIdx.x;
    const int bk  = blockIdx.x;
    const int j0  = bk * 4;

    const float* Whh0 = Whh;
    const float* Wih1 = Wih + 1536 * 512;
    const float* Whh1 = Whh + 1536 * 512;

    // one-time weight preload (persists across all 256 steps)
    for (int idx = tid; idx < 12 * 512; idx += 256) {
        int rl = idx >> 9, k = idx & 511;
        int jj = rl / 3, g = rl % 3;
        ws1[idx] = Whh0[(size_t)(g * Hc + j0 + jj) * Hc + k];
    }
    for (int idx = tid; idx < 24 * 512; idx += 256) {
        int rl = idx >> 9, k = idx & 511;
        int jj = rl / 6, g = rl % 6;
        const float* src = (g < 3) ? Wih1 : Whh1;
        int gg = (g < 3) ? g : g - 3;
        ws2[idx] = src[(size_t)(gg * Hc + j0 + jj) * Hc + k];
    }
    // zero initial hidden state (every launch/replay)
    {
        int i = bk * 256 + tid;
        if (i < Bc * Hc) g_h[i] = 0.f;
    }

    const int out = tid & 127;
    const int b   = out & 31;
    const int jj  = out >> 5;
    const int kh  = tid >> 7;
    const int j   = j0 + jj;

    const float bhh0r = bhh[j],            bhh0z = bhh[Hc + j],            bhh0n = bhh[2 * Hc + j];
    const float bih1r = bih[3 * Hc + j],   bih1z = bih[4 * Hc + j],        bih1n = bih[5 * Hc + j];
    const float bhh1r = bhh[3 * Hc + j],   bhh1z = bhh[4 * Hc + j],        bhh1n = bhh[5 * Hc + j];

    gridbar();   // weights + h=0 visible everywhere

    for (int t = 0; t < Tc; t++) {
        // ----- phase 1: layer 0  (gh0 = h @ Whh0^T, then GRU cell) -----
        for (int i = tid; i < Bc * Hc; i += 256) {
            int bb = i >> 9, k = i & 511;
            hs[k * 33 + bb] = __ldcg(&g_h[i]);
        }
        __syncthreads();
        {
            const float* wr = ws1 + (jj * 3) * Hc + kh * 256;
            const float* wz = wr + Hc;
            const float* wn = wz + Hc;
            const float* hp = hs + (kh * 256) * 33 + b;
            float sr = 0.f, sz = 0.f, sn = 0.f;
#pragma unroll 8
            for (int k = 0; k < 256; k += 4) {
                float4 vr = *(const float4*)(wr + k);
                float4 vz = *(const float4*)(wz + k);
                float4 vn = *(const float4*)(wn + k);
                float h0 = hp[(k + 0) * 33], h1v = hp[(k + 1) * 33];
                float h2 = hp[(k + 2) * 33], h3v = hp[(k + 3) * 33];
                sr += vr.x * h0 + vr.y * h1v + vr.z * h2 + vr.w * h3v;
                sz += vz.x * h0 + vz.y * h1v + vz.z * h2 + vz.w * h3v;
                sn += vn.x * h0 + vn.y * h1v + vn.z * h2 + vn.w * h3v;
            }
            if (kh) { psum[out * 3 + 0] = sr; psum[out * 3 + 1] = sz; psum[out * 3 + 2] = sn; }
            __syncthreads();
            if (!kh) {
                sr += psum[out * 3 + 0]; sz += psum[out * 3 + 1]; sn += psum[out * 3 + 2];
                const float* gi = g_gi0 + (size_t)(t * Bc + b) * 1536;
                float r = sigm(gi[j] + sr + bhh0r);
                float z = sigm(gi[Hc + j] + sz + bhh0z);
                float n = tanhf(gi[2 * Hc + j] + r * (sn + bhh0n));
                float hprev = hs[j * 33 + b];
                g_h1[b * Hc + j] = (1.f - z) * n + z * hprev;
            }
        }
        gridbar();

        // ----- phase 2: layer 1 (input == hidden == h1; fused gi1 & gh1) -----
        for (int i = tid; i < Bc * Hc; i += 256) {
            int bb = i >> 9, k = i & 511;
            hs[k * 33 + bb] = __ldcg(&g_h1[i]);
        }
        __syncthreads();
        {
            const float* w0 = ws2 + (jj * 6) * Hc + kh * 256;
            const float* hp = hs + (kh * 256) * 33 + b;
            float s0 = 0.f, s1 = 0.f, s2 = 0.f, s3 = 0.f, s4 = 0.f, s5 = 0.f;
#pragma unroll 4
            for (int k = 0; k < 256; k += 4) {
                float4 v0 = *(const float4*)(w0 + k);
                float4 v1 = *(const float4*)(w0 + Hc + k);
                float4 v2 = *(const float4*)(w0 + 2 * Hc + k);
                float4 v3 = *(const float4*)(w0 + 3 * Hc + k);
                float4 v4 = *(const float4*)(w0 + 4 * Hc + k);
                float4 v5 = *(const float4*)(w0 + 5 * Hc + k);
                float h0 = hp[(k + 0) * 33], h1v = hp[(k + 1) * 33];
                float h2 = hp[(k + 2) * 33], h3v = hp[(k + 3) * 33];
                s0 += v0.x * h0 + v0.y * h1v + v0.z * h2 + v0.w * h3v;
                s1 += v1.x * h0 + v1.y * h1v + v1.z * h2 + v1.w * h3v;
                s2 += v2.x * h0 + v2.y * h1v + v2.z * h2 + v2.w * h3v;
                s3 += v3.x * h0 + v3.y * h1v + v3.z * h2 + v3.w * h3v;
                s4 += v4.x * h0 + v4.y * h1v + v4.z * h2 + v4.w * h3v;
                s5 += v5.x * h0 + v5.y * h1v + v5.z * h2 + v5.w * h3v;
            }
            if (kh) {
                psum[out * 6 + 0] = s0; psum[out * 6 + 1] = s1; psum[out * 6 + 2] = s2;
                psum[out * 6 + 3] = s3; psum[out * 6 + 4] = s4; psum[out * 6 + 5] = s5;
            }
            __syncthreads();
            if (!kh) {
                s0 += psum[out * 6 + 0]; s1 += psum[out * 6 + 1]; s2 += psum[out * 6 + 2];
                s3 += psum[out * 6 + 3]; s4 += psum[out * 6 + 4]; s5 += psum[out * 6 + 5];
                float r = sigm((s0 + bih1r) + (s3 + bhh1r));
                float z = sigm((s1 + bih1z) + (s4 + bhh1z));
                float n = tanhf((s2 + bih1n) + r * (s5 + bhh1n));
                float h1v = hs[j * 33 + b];
                float h2 = (1.f - z) * n + z * h1v;
                g_h[b * Hc + j] = h2;
                g_outs[(size_t)(b * Tc + t) * Hc + j] = h2;
            }
        }
        gridbar();
    }
}

// ---------------------------------------------------------------------------
// Launch
// ---------------------------------------------------------------------------
extern "C" void kernel_launch(void* const* d_in, const int* in_sizes, int n_in,
                              void* d_out, int out_size)
{
    const int*   x    = (const int*)d_in[0];
    const float* emb  = (const float*)d_in[1];
    const float* Wih  = (const float*)d_in[2];
    const float* Whh  = (const float*)d_in[3];
    const float* bih  = (const float*)d_in[4];
    const float* bhh  = (const float*)d_in[5];
    const float* Wout = (const float*)d_in[6];
    const float* bout = (const float*)d_in[7];
    float* out = (float*)d_out;

    void* p;
    cudaGetSymbolAddress(&p, g_gi0);  float* gi0  = (float*)p;
    cudaGetSymbolAddress(&p, g_outs); float* outs = (float*)p;

    // K1: gi0[t*32+b][0:1536] = emb[x[b][t]] @ Wih0^T + bih0
    dim3 g1(1536 / 128, (Bc * Tc) / 128);
    gemm_tn<1><<<g1, 256>>>(emb, Wih, bih, gi0, x, 1536);

    // K2: persistent recurrence
    size_t smem = REC_SMEM_FLOATS * sizeof(float);   // 144384 B
    cudaFuncSetAttribute(gru_rec, cudaFuncAttributeMaxDynamicSharedMemorySize, (int)smem);
    gru_rec<<<NBLK, 256, smem>>>(Wih, Whh, bih, bhh);

    // K3: logits[b][t][:] = outs[b*T+t] @ Wout^T + bout   (ALPHA = 1)
    dim3 g3(Vc / 128, (Bc * Tc) / 128);
    gemm_tn<0><<<g3, 256>>>(outs, Wout, bout, out, nullptr, Vc);
}

// round 9
// speedup vs baseline: 1.4165x; 1.4165x over previous
#include <cuda_runtime.h>
#include <cuda_bf16.h>
#include <cstdint>

// Problem constants
#define Bc 32
#define Tc 256
#define Hc 512
#define Vc 32000
#define NBLK 128   // persistent recurrence grid (1 block/SM => co-resident)

// K3 split-GEMM constants
#define GKB 1536          // split-K total (3 x 512)
#define KCH 32            // bf16 per K chunk
#define NCHUNK (GKB / KCH) // 48
#define SROW 80           // SMEM row stride bytes (40 halves) -> ldmatrix conflict-free
#define STG_BYTES (128 * SROW)   // 10240 per operand per stage

// ---------------------------------------------------------------------------
// Scratch (device globals: allocation-free per harness rules)
// ---------------------------------------------------------------------------
__device__ float g_gi0[Tc * Bc * 3 * Hc];   // [t*B+b][3H] precomputed input gates L0
__device__ float g_outs[Bc * Tc * Hc];      // [b*T+t][H] GRU outputs
__device__ float g_h[Bc * Hc];
__device__ float g_h1[Bc * Hc];
__device__ unsigned g_barcnt;
__device__ unsigned g_bargen;
// bf16 split operands for tensor-core projection
__device__ __nv_bfloat16 g_abf[(size_t)Bc * Tc * GKB];   // [8192][1536] = [hi|hi|lo]
__device__ __nv_bfloat16 g_bbf[(size_t)Vc * GKB];        // [32000][1536] = [hi|lo|hi]

// ---------------------------------------------------------------------------
// Baseline-ISA PTX helpers (sm_80+ features only; NO 'a'-suffix instructions)
// ---------------------------------------------------------------------------
__device__ __forceinline__ uint32_t smem_u32(const void* p) {
    uint32_t a;
    asm("{ .reg .u64 t; cvta.to.shared.u64 t, %1; cvt.u32.u64 %0, t; }"
        : "=r"(a) : "l"(p));
    return a;
}

#define CP16(dst, src) \
    asm volatile("cp.async.cg.shared.global [%0], [%1], 16;" \
                 :: "r"(dst), "l"(src))
#define CP_COMMIT() asm volatile("cp.async.commit_group;" ::: "memory")
#define CP_WAIT1()  asm volatile("cp.async.wait_group 1;" ::: "memory")

#define LDSM4(r0, r1, r2, r3, addr) \
    asm volatile("ldmatrix.sync.aligned.m8n8.x4.shared.b16 {%0,%1,%2,%3}, [%4];" \
                 : "=r"(r0), "=r"(r1), "=r"(r2), "=r"(r3) : "r"(addr))

#define MMA16816(d, a, b) \
    asm volatile("mma.sync.aligned.m16n8k16.row.col.f32.bf16.bf16.f32 " \
                 "{%0,%1,%2,%3}, {%4,%5,%6,%7}, {%8,%9}, {%0,%1,%2,%3};" \
                 : "+f"((d)[0]), "+f"((d)[1]), "+f"((d)[2]), "+f"((d)[3]) \
                 : "r"((a)[0]), "r"((a)[1]), "r"((a)[2]), "r"((a)[3]), \
                   "r"((b)[0]), "r"((b)[1]))

// ---------------------------------------------------------------------------
// Grid barrier for the recurrence kernel
// ---------------------------------------------------------------------------
__device__ __forceinline__ void gridbar() {
    __syncthreads();
    if (threadIdx.x == 0) {
        __threadfence();
        unsigned gen = *(volatile unsigned*)&g_bargen;
        if (atomicAdd(&g_barcnt, 1u) == NBLK - 1) {
            atomicExch(&g_barcnt, 0u);
            __threadfence();
            atomicAdd(&g_bargen, 1u);
        } else {
            while (*(volatile unsigned*)&g_bargen == gen) __nanosleep(64);
        }
        __threadfence();
    }
    __syncthreads();
}

__device__ __forceinline__ float sigm(float v) { return 1.f / (1.f + __expf(-v)); }

// ---------------------------------------------------------------------------
// K1: fp32 GEMM with fused embedding gather (input-gate precompute)
// ---------------------------------------------------------------------------
template <int MODE>
__global__ void __launch_bounds__(256, 2)
gemm_tn(const float* __restrict__ A, const float* __restrict__ W,
        const float* __restrict__ bias, float* __restrict__ C,
        const int* __restrict__ xidx, int N)
{
    __shared__ float As[16 * 128];
    __shared__ float Bs[16 * 128];

    const int tid  = threadIdx.x;
    const int m0   = blockIdx.y * 128;
    const int n0   = blockIdx.x * 128;
    const int lrow = tid >> 2;
    const int lk   = (tid & 3) * 4;
    const int ty   = tid >> 4;
    const int tx   = tid & 15;

    const float *ap0, *ap1;
    {
        int ma0 = m0 + lrow, ma1 = ma0 + 64;
        if (MODE == 1) {
            int r0 = xidx[(ma0 & 31) * Tc + (ma0 >> 5)];
            int r1 = xidx[(ma1 & 31) * Tc + (ma1 >> 5)];
            ap0 = A + (size_t)r0 * Hc;
            ap1 = A + (size_t)r1 * Hc;
        } else {
            ap0 = A + (size_t)ma0 * Hc;
            ap1 = A + (size_t)ma1 * Hc;
        }
    }
    const float* bp0 = W + (size_t)(n0 + lrow) * Hc;
    const float* bp1 = bp0 + (size_t)64 * Hc;

    float acc[8][8];
#pragma unroll
    for (int i = 0; i < 8; i++)
#pragma unroll
        for (int j = 0; j < 8; j++) acc[i][j] = 0.f;

    for (int kt = 0; kt < Hc; kt += 16) {
        float4 a0 = *(const float4*)(ap0 + kt + lk);
        float4 a1 = *(const float4*)(ap1 + kt + lk);
        float4 b0 = *(const float4*)(bp0 + kt + lk);
        float4 b1 = *(const float4*)(bp1 + kt + lk);
        __syncthreads();
        As[(lk + 0) * 128 + lrow]      = a0.x;
        As[(lk + 1) * 128 + lrow]      = a0.y;
        As[(lk + 2) * 128 + lrow]      = a0.z;
        As[(lk + 3) * 128 + lrow]      = a0.w;
        As[(lk + 0) * 128 + lrow + 64] = a1.x;
        As[(lk + 1) * 128 + lrow + 64] = a1.y;
        As[(lk + 2) * 128 + lrow + 64] = a1.z;
        As[(lk + 3) * 128 + lrow + 64] = a1.w;
        Bs[(lk + 0) * 128 + lrow]      = b0.x;
        Bs[(lk + 1) * 128 + lrow]      = b0.y;
        Bs[(lk + 2) * 128 + lrow]      = b0.z;
        Bs[(lk + 3) * 128 + lrow]      = b0.w;
        Bs[(lk + 0) * 128 + lrow + 64] = b1.x;
        Bs[(lk + 1) * 128 + lrow + 64] = b1.y;
        Bs[(lk + 2) * 128 + lrow + 64] = b1.z;
        Bs[(lk + 3) * 128 + lrow + 64] = b1.w;
        __syncthreads();
#pragma unroll
        for (int kk = 0; kk < 16; kk++) {
            float4 av0 = *(const float4*)&As[kk * 128 + ty * 8];
            float4 av1 = *(const float4*)&As[kk * 128 + ty * 8 + 4];
            float4 bv0 = *(const float4*)&Bs[kk * 128 + tx * 8];
            float4 bv1 = *(const float4*)&Bs[kk * 128 + tx * 8 + 4];
            float a[8] = {av0.x, av0.y, av0.z, av0.w, av1.x, av1.y, av1.z, av1.w};
            float b[8] = {bv0.x, bv0.y, bv0.z, bv0.w, bv1.x, bv1.y, bv1.z, bv1.w};
#pragma unroll
            for (int i = 0; i < 8; i++)
#pragma unroll
                for (int j = 0; j < 8; j++) acc[i][j] += a[i] * b[j];
        }
    }

    float bs[8];
#pragma unroll
    for (int j = 0; j < 8; j++) bs[j] = bias[n0 + tx * 8 + j];
#pragma unroll
    for (int i = 0; i < 8; i++) {
        size_t base = (size_t)(m0 + ty * 8 + i) * (size_t)N + n0 + tx * 8;
        float4 o0 = make_float4(acc[i][0] + bs[0], acc[i][1] + bs[1],
                                acc[i][2] + bs[2], acc[i][3] + bs[3]);
        float4 o1 = make_float4(acc[i][4] + bs[4], acc[i][5] + bs[5],
                                acc[i][6] + bs[6], acc[i][7] + bs[7]);
        *(float4*)&C[base]     = o0;
        *(float4*)&C[base + 4] = o1;
    }
}

// ---------------------------------------------------------------------------
// K2: persistent GRU recurrence (unchanged — passing since R5)
// ---------------------------------------------------------------------------
#define REC_SMEM_FLOATS (12 * 512 + 24 * 512 + 512 * 33 + 768)

__global__ void __launch_bounds__(256, 1)
gru_rec(const float* __restrict__ Wih, const float* __restrict__ Whh,
        const float* __restrict__ bih, const float* __restrict__ bhh)
{
    extern __shared__ float sm[];
    float* ws1  = sm;
    float* ws2  = sm + 12 * 512;
    float* hs   = sm + 36 * 512;
    float* psum = hs + 512 * 33;

    const int tid = threadIdx.x;
    const int bk  = blockIdx.x;
    const int j0  = bk * 4;

    const float* Whh0 = Whh;
    const float* Wih1 = Wih + 1536 * 512;
    const float* Whh1 = Whh + 1536 * 512;

    for (int idx = tid; idx < 12 * 512; idx += 256) {
        int rl = idx >> 9, k = idx & 511;
        int jj = rl / 3, g = rl % 3;
        ws1[idx] = Whh0[(size_t)(g * Hc + j0 + jj) * Hc + k];
    }
    for (int idx = tid; idx < 24 * 512; idx += 256) {
        int rl = idx >> 9, k = idx & 511;
        int jj = rl / 6, g = rl % 6;
        const float* src = (g < 3) ? Wih1 : Whh1;
        int gg = (g < 3) ? g : g - 3;
        ws2[idx] = src[(size_t)(gg * Hc + j0 + jj) * Hc + k];
    }
    {
        int i = bk * 256 + tid;
        if (i < Bc * Hc) g_h[i] = 0.f;
    }

    const int out = tid & 127;
    const int b   = out & 31;
    const int jj  = out >> 5;
    const int kh  = tid >> 7;
    const int j   = j0 + jj;

    const float bhh0r = bhh[j],          bhh0z = bhh[Hc + j],          bhh0n = bhh[2 * Hc + j];
    const float bih1r = bih[3 * Hc + j], bih1z = bih[4 * Hc + j],      bih1n = bih[5 * Hc + j];
    const float bhh1r = bhh[3 * Hc + j], bhh1z = bhh[4 * Hc + j],      bhh1n = bhh[5 * Hc + j];

    gridbar();

    for (int t = 0; t < Tc; t++) {
        for (int i = tid; i < Bc * Hc; i += 256) {
            int bb = i >> 9, k = i & 511;
            hs[k * 33 + bb] = __ldcg(&g_h[i]);
        }
        __syncthreads();
        {
            const float* wr = ws1 + (jj * 3) * Hc + kh * 256;
            const float* wz = wr + Hc;
            const float* wn = wz + Hc;
            const float* hp = hs + (kh * 256) * 33 + b;
            float sr = 0.f, sz = 0.f, sn = 0.f;
#pragma unroll 8
            for (int k = 0; k < 256; k += 4) {
                float4 vr = *(const float4*)(wr + k);
                float4 vz = *(const float4*)(wz + k);
                float4 vn = *(const float4*)(wn + k);
                float h0 = hp[(k + 0) * 33], h1v = hp[(k + 1) * 33];
                float h2 = hp[(k + 2) * 33], h3v = hp[(k + 3) * 33];
                sr += vr.x * h0 + vr.y * h1v + vr.z * h2 + vr.w * h3v;
                sz += vz.x * h0 + vz.y * h1v + vz.z * h2 + vz.w * h3v;
                sn += vn.x * h0 + vn.y * h1v + vn.z * h2 + vn.w * h3v;
            }
            if (kh) { psum[out * 3 + 0] = sr; psum[out * 3 + 1] = sz; psum[out * 3 + 2] = sn; }
            __syncthreads();
            if (!kh) {
                sr += psum[out * 3 + 0]; sz += psum[out * 3 + 1]; sn += psum[out * 3 + 2];
                const float* gi = g_gi0 + (size_t)(t * Bc + b) * 1536;
                float r = sigm(gi[j] + sr + bhh0r);
                float z = sigm(gi[Hc + j] + sz + bhh0z);
                float n = tanhf(gi[2 * Hc + j] + r * (sn + bhh0n));
                float hprev = hs[j * 33 + b];
                g_h1[b * Hc + j] = (1.f - z) * n + z * hprev;
            }
        }
        gridbar();

        for (int i = tid; i < Bc * Hc; i += 256) {
            int bb = i >> 9, k = i & 511;
            hs[k * 33 + bb] = __ldcg(&g_h1[i]);
        }
        __syncthreads();
        {
            const float* w0 = ws2 + (jj * 6) * Hc + kh * 256;
            const float* hp = hs + (kh * 256) * 33 + b;
            float s0 = 0.f, s1 = 0.f, s2 = 0.f, s3 = 0.f, s4 = 0.f, s5 = 0.f;
#pragma unroll 4
            for (int k = 0; k < 256; k += 4) {
                float4 v0 = *(const float4*)(w0 + k);
                float4 v1 = *(const float4*)(w0 + Hc + k);
                float4 v2 = *(const float4*)(w0 + 2 * Hc + k);
                float4 v3 = *(const float4*)(w0 + 3 * Hc + k);
                float4 v4 = *(const float4*)(w0 + 4 * Hc + k);
                float4 v5 = *(const float4*)(w0 + 5 * Hc + k);
                float h0 = hp[(k + 0) * 33], h1v = hp[(k + 1) * 33];
                float h2 = hp[(k + 2) * 33], h3v = hp[(k + 3) * 33];
                s0 += v0.x * h0 + v0.y * h1v + v0.z * h2 + v0.w * h3v;
                s1 += v1.x * h0 + v1.y * h1v + v1.z * h2 + v1.w * h3v;
                s2 += v2.x * h0 + v2.y * h1v + v2.z * h2 + v2.w * h3v;
                s3 += v3.x * h0 + v3.y * h1v + v3.z * h2 + v3.w * h3v;
                s4 += v4.x * h0 + v4.y * h1v + v4.z * h2 + v4.w * h3v;
                s5 += v5.x * h0 + v5.y * h1v + v5.z * h2 + v5.w * h3v;
            }
            if (kh) {
                psum[out * 6 + 0] = s0; psum[out * 6 + 1] = s1; psum[out * 6 + 2] = s2;
                psum[out * 6 + 3] = s3; psum[out * 6 + 4] = s4; psum[out * 6 + 5] = s5;
            }
            __syncthreads();
            if (!kh) {
                s0 += psum[out * 6 + 0]; s1 += psum[out * 6 + 1]; s2 += psum[out * 6 + 2];
                s3 += psum[out * 6 + 3]; s4 += psum[out * 6 + 4]; s5 += psum[out * 6 + 5];
                float r = sigm((s0 + bih1r) + (s3 + bhh1r));
                float z = sigm((s1 + bih1z) + (s4 + bhh1z));
                float n = tanhf((s2 + bih1n) + r * (s5 + bhh1n));
                float h1v = hs[j * 33 + b];
                float h2 = (1.f - z) * n + z * h1v;
                g_h[b * Hc + j] = h2;
                g_outs[(size_t)(b * Tc + t) * Hc + j] = h2;
            }
        }
        gridbar();
    }
}

// ---------------------------------------------------------------------------
// Split-bf16 conversion kernels
// A' row m (= b*T+t): [hi | hi | lo]   from g_outs
// B' row n:           [hi | lo | hi]   from Wout
// ---------------------------------------------------------------------------
__global__ void conv_a() {
    int i = blockIdx.x * 256 + threadIdx.x;
    if (i >= Bc * Tc * Hc) return;
    int m = i >> 9, k = i & 511;
    float x = g_outs[i];
    __nv_bfloat16 hi = __float2bfloat16(x);
    __nv_bfloat16 lo = __float2bfloat16(x - __bfloat162float(hi));
    size_t base = (size_t)m * GKB + k;
    g_abf[base]        = hi;
    g_abf[base + 512]  = hi;
    g_abf[base + 1024] = lo;
}

__global__ void conv_b(const float* __restrict__ Wout) {
    int i = blockIdx.x * 256 + threadIdx.x;
    if (i >= Vc * Hc) return;
    int n = i >> 9, k = i & 511;
    float x = Wout[i];
    __nv_bfloat16 hi = __float2bfloat16(x);
    __nv_bfloat16 lo = __float2bfloat16(x - __bfloat162float(hi));
    size_t base = (size_t)n * GKB + k;
    g_bbf[base]        = hi;
    g_bbf[base + 512]  = lo;
    g_bbf[base + 1024] = hi;
}

// ---------------------------------------------------------------------------
// K3: baseline-ISA HMMA GEMM (mma.sync m16n8k16 bf16), 128x128 tile,
// cp.async double-buffered K-chunks of 32. No 'a'-suffix instructions.
//   8 warps: warp (wm = wid&3, wn = wid>>2) -> 32(M) x 64(N) warp tile
//   SMEM row stride 80B -> ldmatrix bank-conflict-free
// ---------------------------------------------------------------------------
__global__ void __launch_bounds__(256, 2)
gemm_hmma(const float* __restrict__ bout, float* __restrict__ C)
{
    __shared__ __align__(16) char smc[4 * STG_BYTES];   // A[2 stages] + B[2 stages]
    const uint32_t sb = smem_u32(smc);
    const int tid  = threadIdx.x;
    const int lane = tid & 31;
    const int wid  = tid >> 5;
    const int wm   = wid & 3;
    const int wn   = wid >> 2;
    const int m0   = blockIdx.x * 128;   // m fastest: A' (25MB) L2-resident,
    const int n0   = blockIdx.y * 128;   // 64 m-blocks share each B n-tile

    const __nv_bfloat16* Ag = g_abf + (size_t)m0 * GKB;
    const __nv_bfloat16* Bg = g_bbf + (size_t)n0 * GKB;

    float acc[2][8][4];
#pragma unroll
    for (int mb = 0; mb < 2; mb++)
#pragma unroll
        for (int nb = 0; nb < 8; nb++)
#pragma unroll
            for (int q = 0; q < 4; q++) acc[mb][nb][q] = 0.f;

    // chunk loader: 128 rows x 32 halves (64B) per operand, 16B per cp.async
    auto load_chunk = [&](int c) {
        const int s  = c & 1;
        const int kc = c * KCH;
        const uint32_t da = sb + s * STG_BYTES;
        const uint32_t db = sb + 2 * STG_BYTES + s * STG_BYTES;
#pragma unroll
        for (int r = 0; r < 2; r++) {
            int seg = tid + r * 256;          // 512 segs: 128 rows x 4
            int row = seg >> 2, i = seg & 3;
            uint32_t off = (uint32_t)(row * SROW + i * 16);
            CP16(da + off, Ag + (size_t)row * GKB + kc + i * 8);
            CP16(db + off, Bg + (size_t)row * GKB + kc + i * 8);
        }
    };

    load_chunk(0); CP_COMMIT();
    load_chunk(1); CP_COMMIT();

    for (int c = 0; c < NCHUNK; c++) {
        const int s = c & 1;
        CP_WAIT1();                 // chunk c complete (c+1 may be in flight)
        __syncthreads();
        const uint32_t aB = sb + s * STG_BYTES;
        const uint32_t bB = sb + 2 * STG_BYTES + s * STG_BYTES;

#pragma unroll
        for (int kk = 0; kk < 2; kk++) {      // two k16 steps per 32-chunk
            uint32_t a[2][4];
            {
                uint32_t addr = aB + (uint32_t)((wm * 32 + (lane & 15)) * SROW
                                  + (kk * 16 + ((lane >> 4) << 3)) * 2);
                LDSM4(a[0][0], a[0][1], a[0][2], a[0][3], addr);
                LDSM4(a[1][0], a[1][1], a[1][2], a[1][3], addr + 16 * SROW);
            }
            uint32_t b[8][2];
            {
                const int q = lane >> 3, rr = lane & 7;
                const int nbase = wn * 64 + ((q & 2) << 2) + rr;   // +8 for q>=2
                const int kcol  = kk * 16 + ((q & 1) << 3);
#pragma unroll
                for (int p = 0; p < 4; p++) {
                    uint32_t addr = bB + (uint32_t)((nbase + p * 16) * SROW + kcol * 2);
                    LDSM4(b[2 * p][0], b[2 * p][1], b[2 * p + 1][0], b[2 * p + 1][1], addr);
                }
            }
#pragma unroll
            for (int mb = 0; mb < 2; mb++)
#pragma unroll
                for (int nb = 0; nb < 8; nb++)
                    MMA16816(acc[mb][nb], a[mb], b[nb]);
        }

        __syncthreads();
        if (c + 2 < NCHUNK) load_chunk(c + 2);
        CP_COMMIT();                // uniform group accounting (may be empty)
    }

    // epilogue: d-frag (m16n8): rows lane/4 (+8), cols (lane%3)... (lane&3)*2
#pragma unroll
    for (int mb = 0; mb < 2; mb++) {
        const int row = m0 + wm * 32 + mb * 16 + (lane >> 2);
#pragma unroll
        for (int nb = 0; nb < 8; nb++) {
            const int col = n0 + wn * 64 + nb * 8 + (lane & 3) * 2;
            const float b0 = __ldg(&bout[col]);
            const float b1 = __ldg(&bout[col + 1]);
            float2 o0 = make_float2(acc[mb][nb][0] + b0, acc[mb][nb][1] + b1);
            float2 o1 = make_float2(acc[mb][nb][2] + b0, acc[mb][nb][3] + b1);
            *(float2*)&C[(size_t)row * Vc + col]       = o0;
            *(float2*)&C[(size_t)(row + 8) * Vc + col] = o1;
        }
    }
}

// ---------------------------------------------------------------------------
// Launch
// ---------------------------------------------------------------------------
extern "C" void kernel_launch(void* const* d_in, const int* in_sizes, int n_in,
                              void* d_out, int out_size)
{
    const int*   x    = (const int*)d_in[0];
    const float* emb  = (const float*)d_in[1];
    const float* Wih  = (const float*)d_in[2];
    const float* Whh  = (const float*)d_in[3];
    const float* bih  = (const float*)d_in[4];
    const float* bhh  = (const float*)d_in[5];
    const float* Wout = (const float*)d_in[6];
    const float* bout = (const float*)d_in[7];
    float* out = (float*)d_out;

    void* p;
    cudaGetSymbolAddress(&p, g_gi0);  float* gi0 = (float*)p;

    // K1: gi0[t*32+b][0:1536] = emb[x[b][t]] @ Wih0^T + bih0
    dim3 g1(1536 / 128, (Bc * Tc) / 128);
    gemm_tn<1><<<g1, 256>>>(emb, Wih, bih, gi0, x, 1536);

    // B' split conversion (independent of recurrence)
    conv_b<<<(Vc * Hc + 255) / 256, 256>>>(Wout);

    // K2: persistent recurrence
    size_t smem = REC_SMEM_FLOATS * sizeof(float);
    cudaFuncSetAttribute(gru_rec, cudaFuncAttributeMaxDynamicSharedMemorySize, (int)smem);
    gru_rec<<<NBLK, 256, smem>>>(Wih, Whh, bih, bhh);

    // A' split conversion (needs g_outs)
    conv_a<<<(Bc * Tc * Hc + 255) / 256, 256>>>();

    // K3: logits = A' @ B'^T + bout via mma.sync bf16 (split, K'=1536)
    dim3 g3((Bc * Tc) / 128, Vc / 128);   // (64, 250), m fastest
    gemm_hmma<<<g3, 256>>>(bout, out);
}